// round 17
// baseline (speedup 1.0000x reference)
#include <cuda_runtime.h>
#include <cuda_bf16.h>

#define NN 9216
#define WW 96
#define NB 8192
#define CAP 8

// Dynamic shared layout for kernel A (200704 B, needs func attribute):
//   [0)      float    sc[9216]      36864
//   [36864)  unsigned hist[8192]    32768   (packed binstart | cnt<<16 after scan)
//   [69632)  ushort   list[8192*8] 131072
#define SMEM_BYTES 200704

// Cross-kernel handoff: rank | (keep << 31), written coalesced by kernel A.
__device__ unsigned g_rankkeep[NN];

// combo layout: row y, word w(0..3): dec at [y*8+2w], kept at [y*8+2w+1].
// A window-row load is two LDS.64 (uint2) instead of four LDS.32.
__device__ __forceinline__ void set_dec(unsigned* combo, int x, int y) {
    int p = x + 2;
    atomicOr(&combo[y * 8 + 2 * (p >> 5)], 1u << (p & 31));
}
__device__ __forceinline__ void set_kept(unsigned* combo, int x, int y) {
    int p = x + 2;
    atomicOr(&combo[y * 8 + 2 * (p >> 5) + 1], 1u << (p & 31));
}

// ---------------------------------------------------------------------------
// Kernel A: hist + scan + NMS fixpoint + rank/keep pack (coalesced write only;
// scattered output writes live in kernel B on 36 SMs — R16-proven).
// ---------------------------------------------------------------------------
__global__ void __launch_bounds__(1024, 1) nms_rank_kernel(const float* __restrict__ cls) {
    extern __shared__ unsigned char dynsmem[];
    float*          sc   = (float*)dynsmem;
    unsigned*       hist = (unsigned*)(dynsmem + 36864);
    unsigned short* list = (unsigned short*)(dynsmem + 69632);

    // Hot fixpoint state: STATIC shared, dec/kept interleaved for LDS.64.
    __shared__ unsigned combo1[WW * 8], combo2[WW * 8];
    __shared__ unsigned wsum[32];

    const int t    = threadIdx.x;
    const int lane = t & 31, wid = t >> 5;
    const int tx = t & 31, ty = t >> 5;          // band mapping (R9-proven)
    const int x0 = 3 * tx, y0 = 3 * ty;
    const int w  = x0 >> 5, sh = x0 & 31;

    // ---- Phase 0: zero hist + combo arrays ----
    #pragma unroll
    for (int i = 0; i < 8; i++) hist[t * 8 + i] = 0;
    if (t < WW * 8) { combo1[t] = 0; combo2[t] = 0; }
    __syncthreads();

    // ---- Phase 1: load scores; shared histogram + tie lists ----
    #pragma unroll
    for (int k = 0; k < 9; k++) {
        int c = t + k * 1024;
        float s = cls[c];
        sc[c] = s;
        int bin = min((int)(s * 8192.0f), NB - 1);
        unsigned slot = atomicAdd(&hist[bin], 1u);
        if (slot < CAP) list[bin * CAP + slot] = (unsigned short)c;
    }
    __syncthreads();

    // ---- Phase 2: 8192-bin scan (shuffle-based, proven) ----
    {
        unsigned v[8], sum = 0;
        #pragma unroll
        for (int i = 0; i < 8; i++) { v[i] = hist[t * 8 + i]; sum += v[i]; }
        unsigned s = sum;
        #pragma unroll
        for (int off = 1; off < 32; off <<= 1) {
            unsigned n = __shfl_up_sync(0xFFFFFFFFu, s, off);
            if (lane >= off) s += n;
        }
        if (lane == 31) wsum[wid] = s;
        __syncthreads();
        if (wid == 0) {
            unsigned ws = wsum[lane];
            #pragma unroll
            for (int off = 1; off < 32; off <<= 1) {
                unsigned n = __shfl_up_sync(0xFFFFFFFFu, ws, off);
                if (lane >= off) ws += n;
            }
            wsum[lane] = ws;
        }
        __syncthreads();
        unsigned run = (wid ? wsum[wid - 1] : 0u) + s - sum;
        #pragma unroll
        for (int i = 0; i < 8; i++) {
            run += v[i];
            hist[t * 8 + i] = (unsigned)(NN - run) | (v[i] << 16);
        }
    }

    // ---- Phase 3: build masks + init invalid cells (proven logic) ----
    unsigned m1[9];
    unsigned long long m2all = 0;
    unsigned pend = 0;
    #pragma unroll
    for (int k = 0; k < 9; k++) {
        int ry = k / 3, cx = k % 3;
        int x = x0 + cx, y = y0 + ry;
        int c = y * WW + x;
        float s = sc[c];
        unsigned mm1 = 0, n2 = 0;
        if (s > 0.6f) {
            pend |= 1u << k;
            int xm = x % 3, ym = y % 3;
            #define EARLIER(n) (sc[(n)] > s || (sc[(n)] == s && (n) < c))
            if (x > 0  && EARLIER(c - 1))  { mm1 |= 1u << 11; if (xm != 2) n2 |= 2u; }
            if (x < 95 && EARLIER(c + 1))  { mm1 |= 1u << 13; if (xm != 1) n2 |= 4u; }
            if (y > 0  && EARLIER(c - 96)) { mm1 |= 1u << 7;  if (ym != 2) n2 |= 1u; }
            if (y < 95 && EARLIER(c + 96)) { mm1 |= 1u << 17; if (ym != 1) n2 |= 8u; }
            if (x > 1  && xm == 1 && EARLIER(c - 2))   mm1 |= 1u << 10;
            if (x < 94 && xm == 2 && EARLIER(c + 2))   mm1 |= 1u << 14;
            if (y > 1  && ym == 1 && EARLIER(c - 192)) mm1 |= 1u << 2;
            if (y < 94 && ym == 2 && EARLIER(c + 192)) mm1 |= 1u << 22;
            bool sxp4 = (xm == 1), sxm4 = (xm == 2), syp4 = (ym == 1), sym4 = (ym == 2);
            if (x > 0  && y > 0  && !(sxm4 && sym4) && EARLIER(c - 97)) mm1 |= 1u << 6;
            if (x < 95 && y > 0  && !(sxp4 && sym4) && EARLIER(c - 95)) mm1 |= 1u << 8;
            if (x > 0  && y < 95 && !(sxm4 && syp4) && EARLIER(c + 95)) mm1 |= 1u << 16;
            if (x < 95 && y < 95 && !(sxp4 && syp4) && EARLIER(c + 97)) mm1 |= 1u << 18;
            #undef EARLIER
        } else {
            set_dec(combo1, x, y);
            set_dec(combo2, x, y);
        }
        m1[k] = mm1;
        m2all |= (unsigned long long)n2 << (4 * k);
    }
    __syncthreads();

    // ---- Phase 4: deterministic barrier rounds (R9 decisions, LDS.64 loads) ----
    unsigned p1 = pend, p2 = pend;
    for (;;) {
        #pragma unroll
        for (int rep = 0; rep < 2; rep++) {
            if (p1) {
                unsigned dw[7], kw[7];
                #pragma unroll
                for (int r = 0; r < 7; r++) {
                    int ry = y0 - 2 + r;
                    if ((unsigned)ry < WW) {
                        int base = ry * 8 + 2 * w;
                        uint2 a = *(const uint2*)&combo1[base];
                        uint2 b = *(const uint2*)&combo1[base + 2];
                        dw[r] = __funnelshift_r(a.x, b.x, sh) & 0x1FFu;
                        kw[r] = __funnelshift_r(a.y, b.y, sh) & 0x1FFu;
                    } else { dw[r] = 0; kw[r] = 0; }
                }
                #pragma unroll
                for (int k = 0; k < 9; k++) {
                    if (!(p1 & (1u << k))) continue;
                    int ry = k / 3, cx = k % 3;
                    unsigned mk = m1[k], supp = 0, und = 0;
                    #pragma unroll
                    for (int r = 0; r < 5; r++) {
                        unsigned mrow = (mk >> (5 * r)) & 31u;
                        supp |= mrow & (kw[ry + r] >> cx);
                        und  |= mrow & ((~dw[ry + r]) >> cx);
                    }
                    int x = x0 + cx, y = y0 + ry;
                    if (supp) {
                        set_dec(combo1, x, y); set_dec(combo2, x, y);
                        dw[ry + 2] |= 1u << (cx + 2);
                        p1 &= ~(1u << k); p2 &= ~(1u << k);
                    } else if (!und) {
                        set_dec(combo1, x, y); set_kept(combo1, x, y);
                        dw[ry + 2] |= 1u << (cx + 2);
                        kw[ry + 2] |= 1u << (cx + 2);
                        p1 &= ~(1u << k);
                    }
                }
            }
            unsigned ready = p2 & ~p1;
            if (ready) {
                unsigned dw[7], kw[7];
                #pragma unroll
                for (int r = 1; r < 6; r++) {        // pass-2 touches rows 1..5 only
                    int ry = y0 - 2 + r;
                    if ((unsigned)ry < WW) {
                        int base = ry * 8 + 2 * w;
                        uint2 a = *(const uint2*)&combo2[base];
                        uint2 b = *(const uint2*)&combo2[base + 2];
                        dw[r] = __funnelshift_r(a.x, b.x, sh) & 0x1FFu;
                        kw[r] = __funnelshift_r(a.y, b.y, sh) & 0x1FFu;
                    } else { dw[r] = 0; kw[r] = 0; }
                }
                #pragma unroll
                for (int k = 0; k < 9; k++) {
                    if (!(ready & (1u << k))) continue;
                    int ry = k / 3, cx = k % 3;
                    unsigned n2 = (unsigned)(m2all >> (4 * k)) & 15u;
                    unsigned supp =
                          ((n2 >> 0) & (kw[ry + 1] >> (cx + 2)))
                        | ((n2 >> 1) & (kw[ry + 2] >> (cx + 1)))
                        | ((n2 >> 2) & (kw[ry + 2] >> (cx + 3)))
                        | ((n2 >> 3) & (kw[ry + 3] >> (cx + 2)));
                    unsigned und =
                          ((n2 >> 0) & ((~dw[ry + 1]) >> (cx + 2)))
                        | ((n2 >> 1) & ((~dw[ry + 2]) >> (cx + 1)))
                        | ((n2 >> 2) & ((~dw[ry + 2]) >> (cx + 3)))
                        | ((n2 >> 3) & ((~dw[ry + 3]) >> (cx + 2)));
                    int x = x0 + cx, y = y0 + ry;
                    if (supp & 1u) {
                        set_dec(combo2, x, y);
                        dw[ry + 2] |= 1u << (cx + 2);
                        p2 &= ~(1u << k);
                    } else if (!(und & 1u)) {
                        set_dec(combo2, x, y); set_kept(combo2, x, y);
                        dw[ry + 2] |= 1u << (cx + 2);
                        kw[ry + 2] |= 1u << (cx + 2);
                        p2 &= ~(1u << k);
                    }
                }
            }
        }
        if (__syncthreads_and((p1 | p2) == 0)) break;
    }

    // ---- Phase 5: rank + keep pack, COALESCED write only ----
    #pragma unroll
    for (int k = 0; k < 9; k++) {
        int c = t + k * 1024;
        float s = sc[c];
        int bin = min((int)(s * 8192.0f), NB - 1);
        unsigned packed = hist[bin];
        unsigned rank = packed & 0xFFFFu;
        unsigned cnt  = packed >> 16;
        if (cnt > 1u) {
            if (cnt <= CAP) {
                for (unsigned j = 0; j < cnt; j++) {
                    int idx = (int)list[bin * CAP + j];
                    float sj = sc[idx];
                    rank += (sj > s) || (sj == s && idx < c);
                }
            } else {        // overflow fallback: exact recount from shared
                rank = 0;
                for (int j = 0; j < NN; j++) {
                    float sj = sc[j];
                    rank += (sj > s) || (sj == s && j < c);
                }
            }
        }
        int x = c % WW, y = c / WW, p = x + 2;
        unsigned keep = (combo2[y * 8 + 2 * (p >> 5) + 1] >> (p & 31)) & 1u;
        g_rankkeep[c] = rank | (keep << 31);
    }
}

// ---------------------------------------------------------------------------
// Kernel B: multi-SM scatter epilogue (R16-proven).
// ---------------------------------------------------------------------------
__global__ void __launch_bounds__(256) epi_kernel(const float* __restrict__ cls,
                                                  const float* __restrict__ reg,
                                                  float* __restrict__ out) {
    const int c = blockIdx.x * 256 + threadIdx.x;
    unsigned rk = g_rankkeep[c];
    float s  = cls[c];
    float4 d = ((const float4*)reg)[c];
    float kq = (rk >> 31) ? 1.0f : 0.0f;
    int rank = (int)(rk & 0xFFFFu);
    int x = c % WW, y = c / WW;
    float X1 = rintf((2.0f * x) / 0.6f);
    float X2 = rintf((2.0f * x + 12.0f) / 0.6f);
    float Y1 = rintf((2.0f * y) / 0.6f);
    float Y2 = rintf((2.0f * y + 12.0f) / 0.6f);
    float bw = X2 - X1 + 1.0f;
    float bh = Y2 - Y1 + 1.0f;
    float* o = out + rank * 5;
    o[0] = (X1 + d.x * bw) * kq;
    o[1] = (Y1 + d.y * bh) * kq;
    o[2] = (X2 + d.z * bw) * kq;
    o[3] = (Y2 + d.w * bh) * kq;
    o[4] = s * kq;
}

extern "C" void kernel_launch(void* const* d_in, const int* in_sizes, int n_in,
                              void* d_out, int out_size) {
    const float* cls = (const float*)d_in[0];
    const float* reg = (const float*)d_in[1];
    if (n_in >= 2 && in_sizes[0] > in_sizes[1]) {   // defensive: metadata order
        const float* t = cls; cls = reg; reg = t;
    }
    float* out = (float*)d_out;

    cudaFuncSetAttribute(nms_rank_kernel,
                         cudaFuncAttributeMaxDynamicSharedMemorySize, SMEM_BYTES);

    nms_rank_kernel<<<1, 1024, SMEM_BYTES>>>(cls);
    epi_kernel<<<36, 256>>>(cls, reg, out);
}